// round 8
// baseline (speedup 1.0000x reference)
#include <cuda_runtime.h>
#include <cuda_bf16.h>
#include <cstdint>

// YOLO loss: N=64, S=128, B=2.
// input (N,S,S,10) fp32, target (N,S,S,5) fp32 -> 5 fp32 scalars.
// 512 blocks x 256 threads, 8 cells/thread as 4 software-pipelined pair-groups.
// Cheap pass: softplus + ballot-compaction of obj cells (10%) into per-warp
// smem queues; heavy pass (sigmoid/IoU/diffs) runs only on compacted entries.

#define NCELLS (64 * 128 * 128)
#define THREADS 256
#define NWARPS (THREADS / 32)
#define NGROUPS 4                         // pair-groups per thread (2 cells each)
#define PAIRS_PER_BLOCK (THREADS * NGROUPS)   // 1024 pairs = 2048 cells
#define BLOCKS (NCELLS / 2 / PAIRS_PER_BLOCK) // 512
#define CAP 72                            // per-warp obj queue capacity (mean ~26)

__device__ float g_acc[6];   // 0:S_noobj 1:S_xy 2:S_wh 3:S_obj 4:S_nresp 5:m
__device__ unsigned int g_count;

__device__ __forceinline__ float softplus_fast(float x) {
    return fmaxf(x, 0.0f) + __logf(1.0f + __expf(-fabsf(x)));
}
__device__ __forceinline__ float sigmoid_fast(float x) {
    return __fdividef(1.0f, 1.0f + __expf(-x));
}

// Heavy path: only for obj cells. 8 raw coord logits, 4 target coords,
// conf logits + their softplus values.
__device__ __forceinline__ void process_heavy(
    float x0, float y0, float w0, float h0,
    float x1, float y1, float w1, float h1,
    float tx, float ty, float tw, float th,
    float l0, float l1, float b0, float b1,
    float& s_xy, float& s_wh, float& s_obj, float& s_nresp, float& s_m)
{
    float c0x = sigmoid_fast(x0), c0y = sigmoid_fast(y0);
    float c0w = sigmoid_fast(w0), c0h = sigmoid_fast(h0);
    float c1x = sigmoid_fast(x1), c1y = sigmoid_fast(y1);
    float c1w = sigmoid_fast(w1), c1h = sigmoid_fast(h1);

    float tlx = tx - tw * 0.5f, tly = ty - th * 0.5f;
    float trx = tx + tw * 0.5f, trY = ty + th * 0.5f;
    float area_t = tw * th;

    float wx0 = fmaxf(0.0f, fminf(c0x + c0w * 0.5f, trx) - fmaxf(c0x - c0w * 0.5f, tlx));
    float wy0 = fmaxf(0.0f, fminf(c0y + c0h * 0.5f, trY) - fmaxf(c0y - c0h * 0.5f, tly));
    float inter0 = wx0 * wy0;
    float den0 = c0w * c0h + area_t - inter0 + 1e-10f;

    float wx1 = fmaxf(0.0f, fminf(c1x + c1w * 0.5f, trx) - fmaxf(c1x - c1w * 0.5f, tlx));
    float wy1 = fmaxf(0.0f, fminf(c1y + c1h * 0.5f, trY) - fmaxf(c1y - c1h * 0.5f, tly));
    float inter1 = wx1 * wy1;
    float den1 = c1w * c1h + area_t - inter1 + 1e-10f;

    // argmax(iou): box1 wins iff strictly greater (first-max tie-break);
    // denominators > 0 -> cross-product compare, no division.
    bool r1 = inter1 * den0 > inter0 * den1;

    float rx = r1 ? c1x : c0x, ry = r1 ? c1y : c0y;
    float rw = r1 ? c1w : c0w, rh = r1 ? c1h : c0h;
    float rl = r1 ? l1 : l0;
    float rb = r1 ? b1 : b0;
    float nb = r1 ? b0 : b1;

    float dx = rx - tx, dy = ry - ty, dw = rw - tw, dh = rh - th;
    s_xy    += dx * dx + dy * dy;
    s_wh    += dw * dw + dh * dh;
    s_obj   += rb - rl;
    s_nresp += nb;
    s_m     += 1.0f;
}

__shared__ union SmemU {
    float q[NWARPS][CAP][17];   // obj queue: 16 fields, stride 17 (bank-free)
    float red[6][THREADS];      // reused for block reduction
} sm_u;

// Cheap pass for one cell: softplus both confs; noobj accumulate or stash.
__device__ __forceinline__ void process_cell_cheap(
    float l0, float x0, float y0, float w0, float h0,
    float l1, float x1, float y1, float w1, float h1,
    float tconf, float tx, float ty, float tw, float th,
    int warp, int lane, int& cnt,
    float& s_noobj, float& s_xy, float& s_wh,
    float& s_obj, float& s_nresp, float& s_m)
{
    float b0 = softplus_fast(l0);
    float b1 = softplus_fast(l1);
    bool obj = tconf > 0.0f;

    if (!obj) s_noobj += b0 + b1;

    unsigned mask = __ballot_sync(0xffffffffu, obj);
    if (obj) {
        int pos = cnt + __popc(mask & ((1u << lane) - 1u));
        if (pos < CAP) {
            float* e = sm_u.q[warp][pos];
            e[0] = x0;  e[1] = y0;  e[2] = w0;  e[3] = h0;
            e[4] = x1;  e[5] = y1;  e[6] = w1;  e[7] = h1;
            e[8] = tx;  e[9] = ty;  e[10] = tw; e[11] = th;
            e[12] = l0; e[13] = l1; e[14] = b0; e[15] = b1;
        } else {
            // overflow fallback (statistically never at 10% density)
            process_heavy(x0, y0, w0, h0, x1, y1, w1, h1,
                          tx, ty, tw, th, l0, l1, b0, b1,
                          s_xy, s_wh, s_obj, s_nresp, s_m);
        }
    }
    cnt += __popc(mask);
}

__device__ __forceinline__ void process_pair_cheap(
    const float4& i0, const float4& i1, const float4& i2,
    const float4& i3, const float4& i4,
    const float2& t0, const float2& t1, const float2& t2,
    const float2& t3, const float2& t4,
    int warp, int lane, int& cnt,
    float& s_noobj, float& s_xy, float& s_wh,
    float& s_obj, float& s_nresp, float& s_m)
{
    process_cell_cheap(i0.x, i0.y, i0.z, i0.w, i1.x,
                       i1.y, i1.z, i1.w, i2.x, i2.y,
                       t0.x, t0.y, t1.x, t1.y, t2.x,
                       warp, lane, cnt,
                       s_noobj, s_xy, s_wh, s_obj, s_nresp, s_m);
    process_cell_cheap(i2.z, i2.w, i3.x, i3.y, i3.z,
                       i3.w, i4.x, i4.y, i4.z, i4.w,
                       t2.y, t3.x, t3.y, t4.x, t4.y,
                       warp, lane, cnt,
                       s_noobj, s_xy, s_wh, s_obj, s_nresp, s_m);
}

__global__ void __launch_bounds__(THREADS, 2)
yolo_fused_kernel(const float4* __restrict__ inp4, const float2* __restrict__ tgt2,
                  float* __restrict__ out) {
    int tid = threadIdx.x;
    int lane = tid & 31;
    int warp = tid >> 5;
    int base = blockIdx.x * PAIRS_PER_BLOCK;

    float s_noobj = 0.0f, s_xy = 0.0f, s_wh = 0.0f;
    float s_obj = 0.0f, s_nresp = 0.0f, s_m = 0.0f;
    int cnt = 0;   // warp-uniform queue count

    // ---- software-pipelined main loop over 4 pair-groups ----
    int p0 = base + tid;
    const float4* ip = inp4 + (size_t)p0 * 5;
    const float2* tp = tgt2 + (size_t)p0 * 5;
    float4 c0 = ip[0], c1 = ip[1], c2 = ip[2], c3 = ip[3], c4 = ip[4];
    float2 d0 = tp[0], d1 = tp[1], d2 = tp[2], d3 = tp[3], d4 = tp[4];

#pragma unroll
    for (int g = 0; g < NGROUPS; g++) {
        float4 n0, n1, n2, n3, n4;
        float2 m0, m1, m2, m3, m4;
        if (g < NGROUPS - 1) {
            int pn = base + (g + 1) * THREADS + tid;
            const float4* ipn = inp4 + (size_t)pn * 5;
            const float2* tpn = tgt2 + (size_t)pn * 5;
            n0 = ipn[0]; n1 = ipn[1]; n2 = ipn[2]; n3 = ipn[3]; n4 = ipn[4];
            m0 = tpn[0]; m1 = tpn[1]; m2 = tpn[2]; m3 = tpn[3]; m4 = tpn[4];
        }
        process_pair_cheap(c0, c1, c2, c3, c4, d0, d1, d2, d3, d4,
                           warp, lane, cnt,
                           s_noobj, s_xy, s_wh, s_obj, s_nresp, s_m);
        if (g < NGROUPS - 1) {
            c0 = n0; c1 = n1; c2 = n2; c3 = n3; c4 = n4;
            d0 = m0; d1 = m1; d2 = m2; d3 = m3; d4 = m4;
        }
    }

    __syncwarp();
    cnt = min(cnt, CAP);

    // ---- heavy pass: compacted obj cells, ~26 per warp ----
    for (int b = 0; b < cnt; b += 32) {
        int idx = b + lane;
        if (idx < cnt) {
            const float* e = sm_u.q[warp][idx];
            process_heavy(e[0], e[1], e[2], e[3], e[4], e[5], e[6], e[7],
                          e[8], e[9], e[10], e[11], e[12], e[13], e[14], e[15],
                          s_xy, s_wh, s_obj, s_nresp, s_m);
        }
    }

    // ---- block reduction (smem transpose, reusing the queue memory) ----
    __syncthreads();
    sm_u.red[0][tid] = s_noobj;
    sm_u.red[1][tid] = s_xy;
    sm_u.red[2][tid] = s_wh;
    sm_u.red[3][tid] = s_obj;
    sm_u.red[4][tid] = s_nresp;
    sm_u.red[5][tid] = s_m;
    __syncthreads();

    if (warp < 6) {
        float v = 0.0f;
#pragma unroll
        for (int j = 0; j < THREADS / 32; j++)
            v += sm_u.red[warp][lane + j * 32];
#pragma unroll
        for (int off = 16; off > 0; off >>= 1)
            v += __shfl_xor_sync(0xffffffffu, v, off);
        if (lane == 0)
            atomicAdd(&g_acc[warp], v);
    }
    __syncthreads();

    // ---- last block finalizes + resets for the next graph replay ----
    if (tid == 0) {
        __threadfence();
        unsigned int old = atomicAdd(&g_count, 1u);
        if (old == (unsigned int)(gridDim.x - 1)) {
            volatile float* ga = g_acc;
            float a_noobj = ga[0], a_xy = ga[1], a_wh = ga[2];
            float a_obj = ga[3], a_nresp = ga[4], m = ga[5];
            float n_noobj = (float)NCELLS - m;
            float loss_noobj = a_noobj / (n_noobj * 2.0f) + a_nresp / m;  // B=2
            float loss_xy = a_xy / (m * 2.0f);
            float loss_wh = a_wh / (m * 2.0f);
            float loss_obj = a_obj / m;
            out[0] = loss_noobj + loss_xy + loss_wh + loss_obj;
            out[1] = loss_noobj;
            out[2] = loss_xy;
            out[3] = loss_wh;
            out[4] = loss_obj;
#pragma unroll
            for (int k = 0; k < 6; k++) g_acc[k] = 0.0f;
            g_count = 0u;
        }
    }
}

extern "C" void kernel_launch(void* const* d_in, const int* in_sizes, int n_in,
                              void* d_out, int out_size) {
    const float4* inp4 = (const float4*)d_in[0];
    const float2* tgt2 = (const float2*)d_in[1];
    float* out = (float*)d_out;
    yolo_fused_kernel<<<BLOCKS, THREADS>>>(inp4, tgt2, out);
}

// round 9
// speedup vs baseline: 1.1555x; 1.1555x over previous
#include <cuda_runtime.h>
#include <cuda_bf16.h>
#include <cstdint>

// YOLO loss: N=64, S=128, B=2.
// input (N,S,S,10) fp32, target (N,S,S,5) fp32 -> 5 fp32 scalars.
// 512 blocks x 256 threads; each block streams 8 tiles of 256 cells through a
// double-buffered cp.async pipeline (coalesced 16B loads; prefetch t+1 while
// computing t). Branchless per-cell math; smem-transpose block reduction.

#define NCELLS (64 * 128 * 128)
#define THREADS 256
#define NWARPS (THREADS / 32)
#define TILE 256
#define TILES_PER_BLOCK 8
#define BLOCKS (NCELLS / (TILE * TILES_PER_BLOCK))   // 512

#define IN_F4_PER_TILE (TILE * 10 / 4)   // 640 float4
#define TG_F4_PER_TILE (TILE * 5 / 4)    // 320 float4

__device__ float g_acc[6];   // 0:S_noobj 1:S_xy 2:S_wh 3:S_obj 4:S_nresp 5:m
__device__ unsigned int g_count;

__device__ __forceinline__ float softplus_fast(float x) {
    return fmaxf(x, 0.0f) + __logf(1.0f + __expf(-fabsf(x)));
}
__device__ __forceinline__ float sigmoid_fast(float x) {
    return __fdividef(1.0f, 1.0f + __expf(-x));
}
__device__ __forceinline__ void cp_async16(unsigned int smem_addr, const void* gptr) {
    asm volatile("cp.async.cg.shared.global [%0], [%1], 16;"
                 :: "r"(smem_addr), "l"(gptr) : "memory");
}

// Branchless single-cell processing.
__device__ __forceinline__ void process_cell(
    float l0, float x0, float y0, float w0, float h0,
    float l1, float x1, float y1, float w1, float h1,
    float tconf, float tx, float ty, float tw, float th,
    float& s_noobj, float& s_xy, float& s_wh,
    float& s_obj, float& s_nresp, float& s_m)
{
    float obj = (tconf > 0.0f) ? 1.0f : 0.0f;
    float noobj = 1.0f - obj;

    float bce0_0 = softplus_fast(l0);
    float bce0_1 = softplus_fast(l1);

    s_noobj += noobj * (bce0_0 + bce0_1);
    s_m += obj;

    float c0x = sigmoid_fast(x0), c0y = sigmoid_fast(y0);
    float c0w = sigmoid_fast(w0), c0h = sigmoid_fast(h0);
    float c1x = sigmoid_fast(x1), c1y = sigmoid_fast(y1);
    float c1w = sigmoid_fast(w1), c1h = sigmoid_fast(h1);

    float tlx = tx - tw * 0.5f, tly = ty - th * 0.5f;
    float trx = tx + tw * 0.5f, trY = ty + th * 0.5f;
    float area_t = tw * th;

    float wx0 = fmaxf(0.0f, fminf(c0x + c0w * 0.5f, trx) - fmaxf(c0x - c0w * 0.5f, tlx));
    float wy0 = fmaxf(0.0f, fminf(c0y + c0h * 0.5f, trY) - fmaxf(c0y - c0h * 0.5f, tly));
    float inter0 = wx0 * wy0;
    float den0 = c0w * c0h + area_t - inter0 + 1e-10f;

    float wx1 = fmaxf(0.0f, fminf(c1x + c1w * 0.5f, trx) - fmaxf(c1x - c1w * 0.5f, tlx));
    float wy1 = fmaxf(0.0f, fminf(c1y + c1h * 0.5f, trY) - fmaxf(c1y - c1h * 0.5f, tly));
    float inter1 = wx1 * wy1;
    float den1 = c1w * c1h + area_t - inter1 + 1e-10f;

    // argmax(iou): box1 wins iff strictly greater (first-max tie-break);
    // denominators > 0 -> cross-product compare, no division.
    bool r1 = inter1 * den0 > inter0 * den1;

    float rx = r1 ? c1x : c0x, ry = r1 ? c1y : c0y;
    float rw = r1 ? c1w : c0w, rh = r1 ? c1h : c0h;
    float rl = r1 ? l1 : l0;
    float rb = r1 ? bce0_1 : bce0_0;
    float nb = r1 ? bce0_0 : bce0_1;

    float dx = rx - tx, dy = ry - ty, dw = rw - tw, dh = rh - th;
    s_xy    += obj * (dx * dx + dy * dy);
    s_wh    += obj * (dw * dw + dh * dh);
    s_obj   += obj * (rb - rl);
    s_nresp += obj * nb;
}

__shared__ union SmemU {
    struct {
        float in[2][TILE * 10];   // 2 x 10 KB
        float tg[2][TILE * 5];    // 2 x 5 KB
    } pipe;                       // 30 KB
    float red[6][THREADS];        // 6 KB (reused after pipeline drains)
} sm;

__global__ void __launch_bounds__(THREADS)
yolo_fused_kernel(const float* __restrict__ inp, const float* __restrict__ tgt,
                  float* __restrict__ out) {
    int tid = threadIdx.x;
    size_t cell0 = (size_t)blockIdx.x * (TILE * TILES_PER_BLOCK);
    const float* gin = inp + cell0 * 10;
    const float* gtg = tgt + cell0 * 5;

    unsigned int in_addr[2], tg_addr[2];
#pragma unroll
    for (int s = 0; s < 2; s++) {
        in_addr[s] = (unsigned int)__cvta_generic_to_shared(sm.pipe.in[s]);
        tg_addr[s] = (unsigned int)__cvta_generic_to_shared(sm.pipe.tg[s]);
    }

    // prefetch helper (coalesced 16B cp.async, one commit group per tile)
    auto prefetch = [&](int t, int stage) {
        const float* gi = gin + (size_t)t * TILE * 10;
        const float* gt = gtg + (size_t)t * TILE * 5;
#pragma unroll
        for (int i = 0; i < IN_F4_PER_TILE / THREADS; i++) {   // 2 full rounds
            int idx = tid + i * THREADS;
            cp_async16(in_addr[stage] + idx * 16, gi + idx * 4);
        }
        {   // remaining 128 float4 of input
            int idx = tid + (IN_F4_PER_TILE / THREADS) * THREADS;
            if (idx < IN_F4_PER_TILE)
                cp_async16(in_addr[stage] + idx * 16, gi + idx * 4);
        }
        {   // 320 float4 of target: 1 full round + 64
            int idx = tid;
            if (idx < TG_F4_PER_TILE)
                cp_async16(tg_addr[stage] + idx * 16, gt + idx * 4);
            idx = tid + THREADS;
            if (idx < TG_F4_PER_TILE)
                cp_async16(tg_addr[stage] + idx * 16, gt + idx * 4);
        }
        asm volatile("cp.async.commit_group;" ::: "memory");
    };

    float s_noobj = 0.0f, s_xy = 0.0f, s_wh = 0.0f;
    float s_obj = 0.0f, s_nresp = 0.0f, s_m = 0.0f;

    prefetch(0, 0);

#pragma unroll
    for (int t = 0; t < TILES_PER_BLOCK; t++) {
        int stage = t & 1;
        if (t + 1 < TILES_PER_BLOCK)
            prefetch(t + 1, (t + 1) & 1);

        if (t + 1 < TILES_PER_BLOCK)
            asm volatile("cp.async.wait_group 1;" ::: "memory");
        else
            asm volatile("cp.async.wait_group 0;" ::: "memory");
        __syncthreads();

        // process 1 cell per thread from smem
        const float2* ip = reinterpret_cast<const float2*>(sm.pipe.in[stage] + tid * 10);
        float2 a0 = ip[0], a1 = ip[1], a2 = ip[2], a3 = ip[3], a4 = ip[4];
        const float* tp = sm.pipe.tg[stage] + tid * 5;
        float tconf = tp[0], tx = tp[1], ty = tp[2], tw = tp[3], th = tp[4];

        process_cell(a0.x, a0.y, a1.x, a1.y, a2.x,
                     a2.y, a3.x, a3.y, a4.x, a4.y,
                     tconf, tx, ty, tw, th,
                     s_noobj, s_xy, s_wh, s_obj, s_nresp, s_m);

        __syncthreads();   // all reads done before buffer is overwritten
    }

    // ---- block reduction via smem transpose (reuse pipeline smem) ----
    sm.red[0][tid] = s_noobj;
    sm.red[1][tid] = s_xy;
    sm.red[2][tid] = s_wh;
    sm.red[3][tid] = s_obj;
    sm.red[4][tid] = s_nresp;
    sm.red[5][tid] = s_m;
    __syncthreads();

    int lane = tid & 31;
    int warp = tid >> 5;
    if (warp < 6) {
        float v = 0.0f;
#pragma unroll
        for (int j = 0; j < THREADS / 32; j++)
            v += sm.red[warp][lane + j * 32];
#pragma unroll
        for (int off = 16; off > 0; off >>= 1)
            v += __shfl_xor_sync(0xffffffffu, v, off);
        if (lane == 0)
            atomicAdd(&g_acc[warp], v);
    }
    __syncthreads();

    // ---- last block finalizes + resets for the next graph replay ----
    if (tid == 0) {
        __threadfence();
        unsigned int old = atomicAdd(&g_count, 1u);
        if (old == (unsigned int)(gridDim.x - 1)) {
            volatile float* ga = g_acc;
            float a_noobj = ga[0], a_xy = ga[1], a_wh = ga[2];
            float a_obj = ga[3], a_nresp = ga[4], m = ga[5];
            float n_noobj = (float)NCELLS - m;
            float loss_noobj = a_noobj / (n_noobj * 2.0f) + a_nresp / m;  // B=2
            float loss_xy = a_xy / (m * 2.0f);
            float loss_wh = a_wh / (m * 2.0f);
            float loss_obj = a_obj / m;
            out[0] = loss_noobj + loss_xy + loss_wh + loss_obj;
            out[1] = loss_noobj;
            out[2] = loss_xy;
            out[3] = loss_wh;
            out[4] = loss_obj;
#pragma unroll
            for (int k = 0; k < 6; k++) g_acc[k] = 0.0f;
            g_count = 0u;
        }
    }
}

extern "C" void kernel_launch(void* const* d_in, const int* in_sizes, int n_in,
                              void* d_out, int out_size) {
    const float* inp = (const float*)d_in[0];
    const float* tgt = (const float*)d_in[1];
    float* out = (float*)d_out;
    yolo_fused_kernel<<<BLOCKS, THREADS>>>(inp, tgt, out);
}